// round 15
// baseline (speedup 1.0000x reference)
#include <cuda_runtime.h>
#include <cuda_fp16.h>
#include <cstdint>

#define Hh   8
#define Bb   16
#define Gg   512
#define NQq  512
#define Dd   512
#define KDd  64
#define Ee   512
#define NCOL 6144           /* 12 * 512 */
#define ROWSM 8192          /* B * NQ   */
#define NORMS 0.125f

typedef unsigned long long u64;

// ---------------- mma.sync / ldmatrix / cp.async helpers -------------------
__device__ __forceinline__ void ldsm4(uint32_t* d, uint32_t addr) {
    asm volatile("ldmatrix.sync.aligned.m8n8.x4.shared.b16 {%0,%1,%2,%3}, [%4];"
                 : "=r"(d[0]), "=r"(d[1]), "=r"(d[2]), "=r"(d[3]) : "r"(addr));
}
__device__ __forceinline__ void ldsm4t(uint32_t* d, uint32_t addr) {
    asm volatile("ldmatrix.sync.aligned.m8n8.x4.trans.shared.b16 {%0,%1,%2,%3}, [%4];"
                 : "=r"(d[0]), "=r"(d[1]), "=r"(d[2]), "=r"(d[3]) : "r"(addr));
}
__device__ __forceinline__ void mma_f16(float* c, const uint32_t* a,
                                        uint32_t b0, uint32_t b1) {
    asm volatile(
        "mma.sync.aligned.m16n8k16.row.col.f32.f16.f16.f32 "
        "{%0,%1,%2,%3}, {%4,%5,%6,%7}, {%8,%9}, {%0,%1,%2,%3};"
        : "+f"(c[0]), "+f"(c[1]), "+f"(c[2]), "+f"(c[3])
        : "r"(a[0]), "r"(a[1]), "r"(a[2]), "r"(a[3]), "r"(b0), "r"(b1));
}
__device__ __forceinline__ void cpa16(uint32_t dst, const void* src) {
    asm volatile("cp.async.cg.shared.global [%0], [%1], 16;"
                 :: "r"(dst), "l"(src));
}
__device__ __forceinline__ void cpa_commit() {
    asm volatile("cp.async.commit_group;" ::: "memory");
}
__device__ __forceinline__ void cpa_wait1() {
    asm volatile("cp.async.wait_group 1;" ::: "memory");
}
// pack two fp32 as half2 (v0 low, v1 high), plus fp16 residual plane
__device__ __forceinline__ void split_pair(float v0, float v1,
                                           uint32_t& hi, uint32_t& lo) {
    __half2 h = __floats2half2_rn(v0, v1);
    float2 hf = __half22float2(h);
    __half2 l = __floats2half2_rn(v0 - hf.x, v1 - hf.y);
    hi = *reinterpret_cast<uint32_t*>(&h);
    lo = *reinterpret_cast<uint32_t*>(&l);
}

// ---------------- device scratch (static: allocation-guard safe) ----------
__device__ __half g_Phi[(size_t)ROWSM * NCOL];  // projections hi
__device__ __half g_Plo[(size_t)ROWSM * NCOL];  // projections lo
__device__ u64 g_mask[(size_t)Bb * 4 * NQq * 8];

__device__ __half g_Ahi[(size_t)ROWSM * Dd];    // q split
__device__ __half g_Alo[(size_t)ROWSM * Dd];
__device__ __half g_Whi[(size_t)Dd * NCOL];     // fused weights split
__device__ __half g_Wlo[(size_t)Dd * NCOL];
__device__ __half g_Ohi[Dd * Ee];               // W_out split
__device__ __half g_Olo[Dd * Ee];
__device__ __half g_Hhi[(size_t)ROWSM * Dd];    // heads split (B,NQ,H,VD)
__device__ __half g_Hlo[(size_t)ROWSM * Dd];

struct WPtrs { const float* w[12]; };

// ---------------- fused prep: weight repack + q split + wout split --------
#define N_REPACK ((size_t)Dd * NCOL)
#define N_QSPLIT ((size_t)ROWSM * Dd)
#define N_OSPLIT ((size_t)Dd * Ee)
#define PREP_TOTAL (N_REPACK + N_QSPLIT + N_OSPLIT)   /* 7602176 */

__global__ void prep_kernel(WPtrs wp, const float* __restrict__ q,
                            const float* __restrict__ wout) {
    size_t idx = (size_t)blockIdx.x * 256 + threadIdx.x;
    if (idx < N_REPACK) {
        int d   = (int)(idx / NCOL);
        int col = (int)(idx - (size_t)d * NCOL);
        int w   = col >> 9;
        int hk  = col & 511;
        int h   = hk >> 6;
        int k   = hk & 63;
        float x = wp.w[w][((size_t)h * Dd + d) * KDd + k];
        __half hi = __float2half_rn(x);
        g_Whi[idx] = hi;
        g_Wlo[idx] = __float2half_rn(x - __half2float(hi));
    } else if (idx < N_REPACK + N_QSPLIT) {
        size_t i = idx - N_REPACK;
        float x = q[i];
        __half h = __float2half_rn(x);
        g_Ahi[i] = h;
        g_Alo[i] = __float2half_rn(x - __half2float(h));
    } else {
        size_t i = idx - N_REPACK - N_QSPLIT;
        float x = wout[i];
        __half h = __float2half_rn(x);
        g_Ohi[i] = h;
        g_Olo[i] = __float2half_rn(x - __half2float(h));
    }
}

// ---------------- fused mask pack: row branches + transposed branch --------
__global__ void maskall_kernel(const float* __restrict__ attm,
                               const float* __restrict__ gmk,
                               const float* __restrict__ sd) {
    __shared__ float t[64 * 65];
    int bx  = blockIdx.x;
    int tid = threadIdx.x;
    if (bx < 3072) {
        // row-major branches 0,2,3 via ballot (one warp per (b,branch,q))
        int widx = bx * 8 + (tid >> 5);
        int lane = tid & 31;
        int q2 = widx & 511;
        int tt = widx >> 9;
        int br = tt % 3;
        int b  = tt / 3;
        const float* row;
        int c;
        if (br == 0)      { row = sd   + ((size_t)b * 512 + q2) * 512; c = 0; }
        else if (br == 1) { row = attm + ((size_t)b * 512 + q2) * 512; c = 2; }
        else              { row = gmk  + ((size_t)b * 512 + q2) * 512; c = 3; }
#pragma unroll
        for (int tile = 0; tile < 8; tile++) {
            uint32_t b0 = __ballot_sync(0xffffffffu, row[tile * 64 + lane] != 0.0f);
            uint32_t b1 = __ballot_sync(0xffffffffu, row[tile * 64 + 32 + lane] != 0.0f);
            if (lane == 0)
                g_mask[(((size_t)b * 4 + c) * 512 + q2) * 8 + tile] =
                    (u64)b0 | ((u64)b1 << 32);
        }
    } else {
        // transposed branch 1: smem tile + column ballots
        int l  = bx - 3072;          // 0..1023
        int gt = l & 7;
        int qt = (l >> 3) & 7;
        int b  = l >> 6;
        const float* src = attm + ((size_t)b * 512 + gt * 64) * 512 + qt * 64;
#pragma unroll
        for (int it = 0; it < 16; it++) {
            int idx = tid + it * 256;
            int r = idx >> 6, cc = idx & 63;
            t[r * 65 + cc] = src[(size_t)r * 512 + cc];
        }
        __syncthreads();
        int w = tid >> 5, lane = tid & 31;
#pragma unroll
        for (int qq = 0; qq < 8; qq++) {
            int q2 = w * 8 + qq;
            uint32_t b0 = __ballot_sync(0xffffffffu, t[lane * 65 + q2] != 0.0f);
            uint32_t b1 = __ballot_sync(0xffffffffu, t[(lane + 32) * 65 + q2] != 0.0f);
            if (lane == 0)
                g_mask[(((size_t)b * 4 + 1) * 512 + qt * 64 + q2) * 8 + gt] =
                    (u64)b0 | ((u64)b1 << 32);
        }
    }
}

// ---------------- fp16x3 proj GEMM: 128x128 block, 128 thr, 64x64 wtile ---
// 4 warps (2m x 2n), 3-stage cp.async, 2 blocks/SM. Split A-plane passes
// to cap live regs (~180) under the 256 limit (R14 hit the 255 cap).
#define PSTAGE_ELEMS 18944   /* A 2*128*40 + B 2*32*136 */
#define PSMEM_BYTES  (3 * PSTAGE_ELEMS * 2)   /* 113664 */

__global__ __launch_bounds__(128, 2) void proj_gemm_kernel() {
    extern __shared__ __half gsm[];
    uint32_t sb = (uint32_t)__cvta_generic_to_shared(gsm);

    int tid  = threadIdx.x;
    int lane = tid & 31;
    int wid  = tid >> 5;
    int wm   = wid & 1;          // 2 m-warps * 64
    int wn   = wid >> 1;         // 2 n-warps * 64

    int m0 = blockIdx.y * 128;
    int n0 = blockIdx.x * 128;
    int skip_lo = ((n0 >> 9) % 3) == 1;   // K-branch cols: lo plane unread

    float acc[4][8][4];
#pragma unroll
    for (int mf = 0; mf < 4; mf++)
#pragma unroll
        for (int nf = 0; nf < 8; nf++)
#pragma unroll
            for (int e = 0; e < 4; e++) acc[mf][nf][e] = 0.f;

    auto issue = [&](int st, int k0) {
        uint32_t stg = sb + (uint32_t)(st * PSTAGE_ELEMS) * 2;
#pragma unroll
        for (int i = 0; i < 8; i++) {
            int idx = tid + i * 128;
            int p   = idx >> 9;
            int rem = idx & 511;
            int row = rem >> 2, chunk = rem & 3;
            cpa16(stg + (uint32_t)(p * 5120 + row * 40 + chunk * 8) * 2,
                  (p ? g_Alo : g_Ahi) + (size_t)(m0 + row) * Dd + k0 + chunk * 8);
        }
#pragma unroll
        for (int i = 0; i < 8; i++) {
            int idx = tid + i * 128;
            int p   = idx >> 9;
            int rem = idx & 511;
            int row = rem >> 4, chunk = rem & 15;
            cpa16(stg + (uint32_t)(10240 + p * 4352 + row * 136 + chunk * 8) * 2,
                  (p ? g_Wlo : g_Whi) + (size_t)(k0 + row) * NCOL + n0 + chunk * 8);
        }
    };

    issue(0, 0); cpa_commit();
    issue(1, 32); cpa_commit();

    for (int i = 0; i < 16; i++) {       // K=512 / 32
        cpa_wait1();
        __syncthreads();
        uint32_t stg = sb + (uint32_t)((i % 3) * PSTAGE_ELEMS) * 2;

#pragma unroll
        for (int ks = 0; ks < 2; ks++) {
            uint32_t a[4][4];
            // ---- pass 1: A-hi x (B-hi + B-lo) ----
#pragma unroll
            for (int mf = 0; mf < 4; mf++) {
                uint32_t off = (uint32_t)(
                    (wm * 64 + mf * 16 + (lane & 15)) * 40 +
                    ks * 16 + (lane >> 4) * 8) * 2;
                ldsm4(a[mf], stg + off);
            }
#pragma unroll
            for (int pr = 0; pr < 4; pr++) {
                uint32_t bh[4], bl[4];
                uint32_t offh = (uint32_t)(10240 +
                    (ks * 16 + (lane & 15)) * 136 +
                    wn * 64 + pr * 16 + (lane >> 4) * 8) * 2;
                ldsm4t(bh, stg + offh);
                ldsm4t(bl, stg + offh + (uint32_t)4352 * 2);
#pragma unroll
                for (int mf = 0; mf < 4; mf++)
#pragma unroll
                    for (int hh = 0; hh < 2; hh++) {
                        int nf = 2 * pr + hh;
                        mma_f16(acc[mf][nf], a[mf], bh[2 * hh], bh[2 * hh + 1]);
                        mma_f16(acc[mf][nf], a[mf], bl[2 * hh], bl[2 * hh + 1]);
                    }
            }
            // ---- pass 2: A-lo x B-hi ----
#pragma unroll
            for (int mf = 0; mf < 4; mf++) {
                uint32_t off = (uint32_t)(5120 +
                    (wm * 64 + mf * 16 + (lane & 15)) * 40 +
                    ks * 16 + (lane >> 4) * 8) * 2;
                ldsm4(a[mf], stg + off);
            }
#pragma unroll
            for (int pr = 0; pr < 4; pr++) {
                uint32_t bh[4];
                uint32_t offh = (uint32_t)(10240 +
                    (ks * 16 + (lane & 15)) * 136 +
                    wn * 64 + pr * 16 + (lane >> 4) * 8) * 2;
                ldsm4t(bh, stg + offh);
#pragma unroll
                for (int mf = 0; mf < 4; mf++)
#pragma unroll
                    for (int hh = 0; hh < 2; hh++)
                        mma_f16(acc[mf][2 * pr + hh], a[mf], bh[2 * hh], bh[2 * hh + 1]);
            }
        }
        if (i + 2 < 16) issue((i + 2) % 3, (i + 2) * 32);
        cpa_commit();
    }

    // epilogue: split to fp16 hi/lo planes; K-branch cols skip lo
#pragma unroll
    for (int mf = 0; mf < 4; mf++) {
        int gm = m0 + wm * 64 + mf * 16 + (lane >> 2);
#pragma unroll
        for (int nf = 0; nf < 8; nf++) {
            int gn = n0 + wn * 64 + nf * 8 + (lane & 3) * 2;
            uint32_t h2, l2;
            split_pair(acc[mf][nf][0], acc[mf][nf][1], h2, l2);
            *(uint32_t*)(g_Phi + (size_t)gm * NCOL + gn) = h2;
            if (!skip_lo) *(uint32_t*)(g_Plo + (size_t)gm * NCOL + gn) = l2;
            split_pair(acc[mf][nf][2], acc[mf][nf][3], h2, l2);
            *(uint32_t*)(g_Phi + (size_t)(gm + 8) * NCOL + gn) = h2;
            if (!skip_lo) *(uint32_t*)(g_Plo + (size_t)(gm + 8) * NCOL + gn) = l2;
        }
    }
}

// ---------------- fp16x3 pipelined MMA GEMM (3-stage, output proj) --------
#define GSTAGE_ELEMS 18944          /* 2*128*40 + 2*32*136 */
#define GSMEM_BYTES  (3 * GSTAGE_ELEMS * 2)

__global__ __launch_bounds__(256) void mma_gemm2_kernel(
    const __half* __restrict__ Ahi, const __half* __restrict__ Alo,
    const __half* __restrict__ Bhi, const __half* __restrict__ Blo,
    float* __restrict__ C, int M, int N, int K) {
    extern __shared__ __half gsm[];
    uint32_t sb = (uint32_t)__cvta_generic_to_shared(gsm);

    int tid  = threadIdx.x;
    int lane = tid & 31;
    int wid  = tid >> 5;
    int wm   = wid & 1;
    int wn   = wid >> 1;

    int m0 = blockIdx.y * 128;
    int n0 = blockIdx.x * 128;

    const __half* Ag[2] = { Ahi, Alo };
    const __half* Bg[2] = { Bhi, Blo };

    float acc[4][4][4];
#pragma unroll
    for (int mf = 0; mf < 4; mf++)
#pragma unroll
        for (int nf = 0; nf < 4; nf++)
#pragma unroll
            for (int e = 0; e < 4; e++) acc[mf][nf][e] = 0.f;

    int arow = tid >> 1;
    int achk = tid & 1;
    int brow = tid >> 3;
    int bchk = tid & 7;

    int steps = K >> 5;

    auto issue = [&](int st, int k0) {
        uint32_t stg = sb + (uint32_t)(st * GSTAGE_ELEMS) * 2;
#pragma unroll
        for (int p = 0; p < 2; p++) {
#pragma unroll
            for (int cc = 0; cc < 2; cc++) {
                int chunk = achk + cc * 2;
                cpa16(stg + (uint32_t)(p * 5120 + arow * 40 + chunk * 8) * 2,
                      Ag[p] + (size_t)(m0 + arow) * K + k0 + chunk * 8);
            }
#pragma unroll
            for (int cc = 0; cc < 2; cc++) {
                int chunk = bchk + cc * 8;
                cpa16(stg + (uint32_t)(10240 + p * 4352 + brow * 136 + chunk * 8) * 2,
                      Bg[p] + (size_t)(k0 + brow) * N + n0 + chunk * 8);
            }
        }
    };

    issue(0, 0); cpa_commit();
    issue(1, 32); cpa_commit();

    for (int i = 0; i < steps; i++) {
        cpa_wait1();
        __syncthreads();
        uint32_t stg = sb + (uint32_t)((i % 3) * GSTAGE_ELEMS) * 2;

#pragma unroll
        for (int ks = 0; ks < 2; ks++) {
            uint32_t a[2][4][4];
#pragma unroll
            for (int p = 0; p < 2; p++)
#pragma unroll
                for (int mf = 0; mf < 4; mf++) {
                    uint32_t off = (uint32_t)(p * 5120 +
                        (wm * 64 + mf * 16 + (lane & 15)) * 40 +
                        ks * 16 + (lane >> 4) * 8) * 2;
                    ldsm4(a[p][mf], stg + off);
                }
#pragma unroll
            for (int pr = 0; pr < 2; pr++) {
                uint32_t bh[4], bl[4];
                uint32_t offh = (uint32_t)(10240 +
                    (ks * 16 + (lane & 15)) * 136 +
                    wn * 32 + pr * 16 + (lane >> 4) * 8) * 2;
                ldsm4t(bh, stg + offh);
                ldsm4t(bl, stg + offh + (uint32_t)4352 * 2);
#pragma unroll
                for (int mf = 0; mf < 4; mf++) {
#pragma unroll
                    for (int hh = 0; hh < 2; hh++) {
                        int nf = 2 * pr + hh;
                        mma_f16(acc[mf][nf], a[0][mf], bh[2 * hh], bh[2 * hh + 1]);
                        mma_f16(acc[mf][nf], a[0][mf], bl[2 * hh], bl[2 * hh + 1]);
                        mma_f16(acc[mf][nf], a[1][mf], bh[2 * hh], bh[2 * hh + 1]);
                    }
                }
            }
        }
        if (i + 2 < steps) issue((i + 2) % 3, (i + 2) * 32);
        cpa_commit();
    }

#pragma unroll
    for (int mf = 0; mf < 4; mf++) {
        int gm = m0 + wm * 64 + mf * 16 + (lane >> 2);
#pragma unroll
        for (int nf = 0; nf < 4; nf++) {
            int gn = n0 + wn * 32 + nf * 8 + (lane & 3) * 2;
            *(float2*)(C + (size_t)gm * N + gn) =
                make_float2(acc[mf][nf][0], acc[mf][nf][1]);
            *(float2*)(C + (size_t)(gm + 8) * N + gn) =
                make_float2(acc[mf][nf][2], acc[mf][nf][3]);
        }
    }
}

// ---------------- tensor-core fused attention (fp16, v5 — R10 best) --------
#define QSTR 72
#define ATTN_SMEM ((2 * 128 + 3 * 64) * QSTR * 2)   /* 64512 B */

__global__ __launch_bounds__(128, 3) void attn_mma_kernel() {
    extern __shared__ __half sm[];
    __half* Qhi = sm;
    __half* Qlo = Qhi + 128 * QSTR;
    __half* Khi = Qlo + 128 * QSTR;
    __half* Vhi = Khi + 64 * QSTR;
    __half* Vlo = Vhi + 64 * QSTR;

    int qt = blockIdx.x;
    int hb = blockIdx.y;
    int b  = hb >> 3;
    int h  = hb & 7;
    int tid  = threadIdx.x;
    int lane = tid & 31;
    int wq   = tid >> 5;

    uint32_t qhi_b = (uint32_t)__cvta_generic_to_shared(Qhi);
    uint32_t qlo_b = (uint32_t)__cvta_generic_to_shared(Qlo);
    uint32_t khi_b = (uint32_t)__cvta_generic_to_shared(Khi);
    uint32_t vhi_b = (uint32_t)__cvta_generic_to_shared(Vhi);
    uint32_t vlo_b = (uint32_t)__cvta_generic_to_shared(Vlo);

    float o[2][8][4];
    float mrow[2][2], den[2][2];
#pragma unroll
    for (int mf = 0; mf < 2; mf++) {
#pragma unroll
        for (int vf = 0; vf < 8; vf++)
#pragma unroll
            for (int e = 0; e < 4; e++) o[mf][vf][e] = 0.f;
        mrow[mf][0] = mrow[mf][1] = -1e30f;
        den[mf][0] = den[mf][1] = 0.f;
    }

    int ldr = tid >> 3;
    int c8  = tid & 7;
    const __half2 nrm2 = __floats2half2_rn(NORMS, NORMS);

    for (int c = 0; c < 4; c++) {
        __syncthreads();
        {
            size_t qoff = (size_t)(b * 512 + qt * 128) * NCOL + (3 * c) * 512
                          + h * 64 + c8 * 8;
#pragma unroll
            for (int it = 0; it < 8; it++) {
                int row = ldr + it * 16;
                __half2 v[4];
                *(uint4*)v = *(const uint4*)(g_Phi + qoff + (size_t)row * NCOL);
#pragma unroll
                for (int e = 0; e < 4; e++) v[e] = __hmul2(v[e], nrm2);
                *(uint4*)(Qhi + row * QSTR + c8 * 8) = *(uint4*)v;
                *(uint4*)v = *(const uint4*)(g_Plo + qoff + (size_t)row * NCOL);
#pragma unroll
                for (int e = 0; e < 4; e++) v[e] = __hmul2(v[e], nrm2);
                *(uint4*)(Qlo + row * QSTR + c8 * 8) = *(uint4*)v;
            }
        }
        size_t mrow_base = (((size_t)b * 4 + c) * 512 + qt * 128) * 8;

        for (int g0t = 0; g0t < 8; g0t++) {
            __syncthreads();
            {
                size_t gbase = (size_t)(b * 512 + g0t * 64) * NCOL + h * 64 + c8 * 8;
                const __half* KgH = g_Phi + gbase + (3 * c + 1) * 512;
                const __half* VgH = g_Phi + gbase + (3 * c + 2) * 512;
                const __half* VgL = g_Plo + gbase + (3 * c + 2) * 512;
#pragma unroll
                for (int it = 0; it < 4; it++) {
                    int row = ldr + it * 16;
                    *(uint4*)(Khi + row * QSTR + c8 * 8) = *(const uint4*)(KgH + (size_t)row * NCOL);
                    *(uint4*)(Vhi + row * QSTR + c8 * 8) = *(const uint4*)(VgH + (size_t)row * NCOL);
                    *(uint4*)(Vlo + row * QSTR + c8 * 8) = *(const uint4*)(VgL + (size_t)row * NCOL);
                }
            }
            __syncthreads();

            u64 mw[2][2];
#pragma unroll
            for (int mf = 0; mf < 2; mf++)
#pragma unroll
                for (int hf = 0; hf < 2; hf++) {
                    int ql = wq * 32 + mf * 16 + (lane >> 2) + 8 * hf;
                    mw[mf][hf] = g_mask[mrow_base + (size_t)ql * 8 + g0t];
                }

            float s[2][8][4];
#pragma unroll
            for (int mf = 0; mf < 2; mf++)
#pragma unroll
                for (int nf = 0; nf < 8; nf++)
#pragma unroll
                    for (int e = 0; e < 4; e++) s[mf][nf][e] = 0.f;

#pragma unroll
            for (int ks = 0; ks < 4; ks++) {
                uint32_t ah[2][4], al[2][4];
#pragma unroll
                for (int mf = 0; mf < 2; mf++) {
                    uint32_t off = ((wq * 32 + mf * 16 + (lane & 15)) * QSTR +
                                    ks * 16 + (lane >> 4) * 8) * 2;
                    ldsm4(ah[mf], qhi_b + off);
                    ldsm4(al[mf], qlo_b + off);
                }
#pragma unroll
                for (int pr = 0; pr < 4; pr++) {
                    uint32_t off = ((pr * 16 + (lane & 7) + ((lane >> 4) & 1) * 8) * QSTR +
                                    ks * 16 + ((lane >> 3) & 1) * 8) * 2;
                    uint32_t kh[4];
                    ldsm4(kh, khi_b + off);
#pragma unroll
                    for (int mf = 0; mf < 2; mf++) {
                        mma_f16(s[mf][2 * pr],     ah[mf], kh[0], kh[1]);
                        mma_f16(s[mf][2 * pr],     al[mf], kh[0], kh[1]);
                        mma_f16(s[mf][2 * pr + 1], ah[mf], kh[2], kh[3]);
                        mma_f16(s[mf][2 * pr + 1], al[mf], kh[2], kh[3]);
                    }
                }
            }

#pragma unroll
            for (int mf = 0; mf < 2; mf++)
#pragma unroll
                for (int hf = 0; hf < 2; hf++) {
                    int i0 = 2 * hf;
                    u64 w = mw[mf][hf];
                    int sb2 = 2 * (lane & 3);
                    float rm = -1e30f;
#pragma unroll
                    for (int nf = 0; nf < 8; nf++) {
                        uint32_t bits = (uint32_t)(w >> (nf * 8 + sb2)) & 3u;
                        float v0 = (bits & 1u) ? s[mf][nf][i0] : -1e30f;
                        float v1 = (bits & 2u) ? s[mf][nf][i0 + 1] : -1e30f;
                        s[mf][nf][i0]     = v0;
                        s[mf][nf][i0 + 1] = v1;
                        rm = fmaxf(rm, fmaxf(v0, v1));
                    }
                    rm = fmaxf(rm, __shfl_xor_sync(0xffffffffu, rm, 1));
                    rm = fmaxf(rm, __shfl_xor_sync(0xffffffffu, rm, 2));
                    float mo = mrow[mf][hf];
                    float mn = fmaxf(mo, rm);
                    float rs = 0.f;
#pragma unroll
                    for (int nf = 0; nf < 8; nf++) {
                        float v0 = s[mf][nf][i0];
                        float v1 = s[mf][nf][i0 + 1];
                        float p0 = (v0 > -1e29f) ? __expf(v0 - mn) : 0.f;
                        float p1 = (v1 > -1e29f) ? __expf(v1 - mn) : 0.f;
                        s[mf][nf][i0]     = p0;
                        s[mf][nf][i0 + 1] = p1;
                        rs += p0 + p1;
                    }
                    rs += __shfl_xor_sync(0xffffffffu, rs, 1);
                    rs += __shfl_xor_sync(0xffffffffu, rs, 2);
                    if (mn > mo) {
                        float sc = __expf(mo - mn);
                        den[mf][hf] = den[mf][hf] * sc + rs;
#pragma unroll
                        for (int vf = 0; vf < 8; vf++) {
                            o[mf][vf][i0]     *= sc;
                            o[mf][vf][i0 + 1] *= sc;
                        }
                    } else {
                        den[mf][hf] += rs;
                    }
                    mrow[mf][hf] = mn;
                }

#pragma unroll
            for (int ks = 0; ks < 4; ks++) {
                uint32_t ph[2][4], pl[2][4];
#pragma unroll
                for (int mf = 0; mf < 2; mf++) {
                    split_pair(s[mf][2 * ks][0],     s[mf][2 * ks][1],     ph[mf][0], pl[mf][0]);
                    split_pair(s[mf][2 * ks][2],     s[mf][2 * ks][3],     ph[mf][1], pl[mf][1]);
                    split_pair(s[mf][2 * ks + 1][0], s[mf][2 * ks + 1][1], ph[mf][2], pl[mf][2]);
                    split_pair(s[mf][2 * ks + 1][2], s[mf][2 * ks + 1][3], ph[mf][3], pl[mf][3]);
                }
#pragma unroll
                for (int pr = 0; pr < 4; pr++) {
                    uint32_t off = ((ks * 16 + (lane & 15)) * QSTR +
                                    pr * 16 + (lane >> 4) * 8) * 2;
                    uint32_t vh[4], vl[4];
                    ldsm4t(vh, vhi_b + off);
                    ldsm4t(vl, vlo_b + off);
#pragma unroll
                    for (int mf = 0; mf < 2; mf++) {
                        mma_f16(o[mf][2 * pr],     ph[mf], vh[0], vh[1]);
                        mma_f16(o[mf][2 * pr],     ph[mf], vl[0], vl[1]);
                        mma_f16(o[mf][2 * pr],     pl[mf], vh[0], vh[1]);
                        mma_f16(o[mf][2 * pr + 1], ph[mf], vh[2], vh[3]);
                        mma_f16(o[mf][2 * pr + 1], ph[mf], vl[2], vl[3]);
                        mma_f16(o[mf][2 * pr + 1], pl[mf], vh[2], vh[3]);
                    }
                }
            }
        }
        __syncthreads();
    }

#pragma unroll
    for (int mf = 0; mf < 2; mf++)
#pragma unroll
        for (int hf = 0; hf < 2; hf++) {
            int ql = wq * 32 + mf * 16 + (lane >> 2) + 8 * hf;
            float dv = den[mf][hf];
            float inv = (dv > 0.f) ? 1.f / dv : 0.f;
            size_t base = ((size_t)(b * 512 + qt * 128 + ql)) * 512 + h * 64;
#pragma unroll
            for (int vf = 0; vf < 8; vf++) {
                float v0 = o[mf][vf][2 * hf] * inv;
                float v1 = o[mf][vf][2 * hf + 1] * inv;
                uint32_t h2, l2;
                split_pair(v0, v1, h2, l2);
                int col = vf * 8 + 2 * (lane & 3);
                *(uint32_t*)(g_Hhi + base + col) = h2;
                *(uint32_t*)(g_Hlo + base + col) = l2;
            }
        }
}

// ---------------- launch ---------------------------------------------------
extern "C" void kernel_launch(void* const* d_in, const int* in_sizes, int n_in,
                              void* d_out, int out_size) {
    const float* q    = (const float*)d_in[0];
    const float* attM = (const float*)d_in[1];
    const float* grpM = (const float*)d_in[2];
    const float* sdM  = (const float*)d_in[3];
    WPtrs wp;
    for (int i = 0; i < 12; i++) wp.w[i] = (const float*)d_in[4 + i];
    const float* wout = (const float*)d_in[16];
    float* out = (float*)d_out;

    void *pAhi, *pAlo, *pOhi, *pOlo, *pHhi, *pHlo;
    cudaGetSymbolAddress(&pAhi, g_Ahi);
    cudaGetSymbolAddress(&pAlo, g_Alo);
    cudaGetSymbolAddress(&pOhi, g_Ohi);
    cudaGetSymbolAddress(&pOlo, g_Olo);
    cudaGetSymbolAddress(&pHhi, g_Hhi);
    cudaGetSymbolAddress(&pHlo, g_Hlo);

    cudaFuncSetAttribute(proj_gemm_kernel,
                         cudaFuncAttributeMaxDynamicSharedMemorySize, PSMEM_BYTES);
    cudaFuncSetAttribute(mma_gemm2_kernel,
                         cudaFuncAttributeMaxDynamicSharedMemorySize, GSMEM_BYTES);
    cudaFuncSetAttribute(attn_mma_kernel,
                         cudaFuncAttributeMaxDynamicSharedMemorySize, ATTN_SMEM);

    // ncu capture slot (index 3) = attention this round
    // 0: fused prep (weight repack + q split + wout split)
    prep_kernel<<<(int)(PREP_TOTAL / 256), 256>>>(wp, q, wout);
    // 1: all mask packing
    maskall_kernel<<<4096, 256>>>(attM, grpM, sdM);
    // 2: fused projection GEMM -> fp16 hi/lo planes
    proj_gemm_kernel<<<dim3(NCOL / 128, ROWSM / 128), 128, PSMEM_BYTES>>>();
    // 3: tensor-core fused masked 4-branch attention
    attn_mma_kernel<<<dim3(4, 128), 128, ATTN_SMEM>>>();
    // 4: output GEMM -> fp32 out (3-stage)
    mma_gemm2_kernel<<<dim3(Ee / 128, ROWSM / 128), 256, GSMEM_BYTES>>>(
        (const __half*)pHhi, (const __half*)pHlo,
        (const __half*)pOhi, (const __half*)pOlo,
        out, ROWSM, Ee, Dd);
}

// round 16
// speedup vs baseline: 1.0352x; 1.0352x over previous
#include <cuda_runtime.h>
#include <cuda_fp16.h>
#include <cstdint>

#define Hh   8
#define Bb   16
#define Gg   512
#define NQq  512
#define Dd   512
#define KDd  64
#define Ee   512
#define NCOL 6144           /* 12 * 512 */
#define ROWSM 8192          /* B * NQ   */
#define NORMS 0.125f

typedef unsigned long long u64;

// ---------------- mma.sync / ldmatrix / cp.async helpers -------------------
__device__ __forceinline__ void ldsm4(uint32_t* d, uint32_t addr) {
    asm volatile("ldmatrix.sync.aligned.m8n8.x4.shared.b16 {%0,%1,%2,%3}, [%4];"
                 : "=r"(d[0]), "=r"(d[1]), "=r"(d[2]), "=r"(d[3]) : "r"(addr));
}
__device__ __forceinline__ void ldsm4t(uint32_t* d, uint32_t addr) {
    asm volatile("ldmatrix.sync.aligned.m8n8.x4.trans.shared.b16 {%0,%1,%2,%3}, [%4];"
                 : "=r"(d[0]), "=r"(d[1]), "=r"(d[2]), "=r"(d[3]) : "r"(addr));
}
__device__ __forceinline__ void mma_f16(float* c, const uint32_t* a,
                                        uint32_t b0, uint32_t b1) {
    asm volatile(
        "mma.sync.aligned.m16n8k16.row.col.f32.f16.f16.f32 "
        "{%0,%1,%2,%3}, {%4,%5,%6,%7}, {%8,%9}, {%0,%1,%2,%3};"
        : "+f"(c[0]), "+f"(c[1]), "+f"(c[2]), "+f"(c[3])
        : "r"(a[0]), "r"(a[1]), "r"(a[2]), "r"(a[3]), "r"(b0), "r"(b1));
}
__device__ __forceinline__ void cpa16(uint32_t dst, const void* src) {
    asm volatile("cp.async.cg.shared.global [%0], [%1], 16;"
                 :: "r"(dst), "l"(src));
}
__device__ __forceinline__ void cpa_commit() {
    asm volatile("cp.async.commit_group;" ::: "memory");
}
__device__ __forceinline__ void cpa_wait1() {
    asm volatile("cp.async.wait_group 1;" ::: "memory");
}
// pack two fp32 as half2 (v0 low, v1 high), plus fp16 residual plane
__device__ __forceinline__ void split_pair(float v0, float v1,
                                           uint32_t& hi, uint32_t& lo) {
    __half2 h = __floats2half2_rn(v0, v1);
    float2 hf = __half22float2(h);
    __half2 l = __floats2half2_rn(v0 - hf.x, v1 - hf.y);
    hi = *reinterpret_cast<uint32_t*>(&h);
    lo = *reinterpret_cast<uint32_t*>(&l);
}

// ---------------- device scratch (static: allocation-guard safe) ----------
__device__ __half g_Phi[(size_t)ROWSM * NCOL];  // projections hi
__device__ __half g_Plo[(size_t)ROWSM * NCOL];  // projections lo
__device__ u64 g_mask[(size_t)Bb * 4 * NQq * 8];

__device__ __half g_Ahi[(size_t)ROWSM * Dd];    // q split
__device__ __half g_Alo[(size_t)ROWSM * Dd];
__device__ __half g_Whi[(size_t)Dd * NCOL];     // fused weights split
__device__ __half g_Wlo[(size_t)Dd * NCOL];
__device__ __half g_Ohi[Dd * Ee];               // W_out split
__device__ __half g_Olo[Dd * Ee];
__device__ __half g_Hhi[(size_t)ROWSM * Dd];    // heads split (B,NQ,H,VD)
__device__ __half g_Hlo[(size_t)ROWSM * Dd];

struct WPtrs { const float* w[12]; };

// ---------------- fused prep: weight repack + q split + wout split --------
#define N_REPACK ((size_t)Dd * NCOL)
#define N_QSPLIT ((size_t)ROWSM * Dd)
#define N_OSPLIT ((size_t)Dd * Ee)
#define PREP_TOTAL (N_REPACK + N_QSPLIT + N_OSPLIT)   /* 7602176 */

__global__ void prep_kernel(WPtrs wp, const float* __restrict__ q,
                            const float* __restrict__ wout) {
    size_t idx = (size_t)blockIdx.x * 256 + threadIdx.x;
    if (idx < N_REPACK) {
        int d   = (int)(idx / NCOL);
        int col = (int)(idx - (size_t)d * NCOL);
        int w   = col >> 9;
        int hk  = col & 511;
        int h   = hk >> 6;
        int k   = hk & 63;
        float x = wp.w[w][((size_t)h * Dd + d) * KDd + k];
        __half hi = __float2half_rn(x);
        g_Whi[idx] = hi;
        g_Wlo[idx] = __float2half_rn(x - __half2float(hi));
    } else if (idx < N_REPACK + N_QSPLIT) {
        size_t i = idx - N_REPACK;
        float x = q[i];
        __half h = __float2half_rn(x);
        g_Ahi[i] = h;
        g_Alo[i] = __float2half_rn(x - __half2float(h));
    } else {
        size_t i = idx - N_REPACK - N_QSPLIT;
        float x = wout[i];
        __half h = __float2half_rn(x);
        g_Ohi[i] = h;
        g_Olo[i] = __float2half_rn(x - __half2float(h));
    }
}

// ---------------- fused mask pack: row branches + transposed branch --------
__global__ void maskall_kernel(const float* __restrict__ attm,
                               const float* __restrict__ gmk,
                               const float* __restrict__ sd) {
    __shared__ float t[64 * 65];
    int bx  = blockIdx.x;
    int tid = threadIdx.x;
    if (bx < 3072) {
        int widx = bx * 8 + (tid >> 5);
        int lane = tid & 31;
        int q2 = widx & 511;
        int tt = widx >> 9;
        int br = tt % 3;
        int b  = tt / 3;
        const float* row;
        int c;
        if (br == 0)      { row = sd   + ((size_t)b * 512 + q2) * 512; c = 0; }
        else if (br == 1) { row = attm + ((size_t)b * 512 + q2) * 512; c = 2; }
        else              { row = gmk  + ((size_t)b * 512 + q2) * 512; c = 3; }
#pragma unroll
        for (int tile = 0; tile < 8; tile++) {
            uint32_t b0 = __ballot_sync(0xffffffffu, row[tile * 64 + lane] != 0.0f);
            uint32_t b1 = __ballot_sync(0xffffffffu, row[tile * 64 + 32 + lane] != 0.0f);
            if (lane == 0)
                g_mask[(((size_t)b * 4 + c) * 512 + q2) * 8 + tile] =
                    (u64)b0 | ((u64)b1 << 32);
        }
    } else {
        int l  = bx - 3072;
        int gt = l & 7;
        int qt = (l >> 3) & 7;
        int b  = l >> 6;
        const float* src = attm + ((size_t)b * 512 + gt * 64) * 512 + qt * 64;
#pragma unroll
        for (int it = 0; it < 16; it++) {
            int idx = tid + it * 256;
            int r = idx >> 6, cc = idx & 63;
            t[r * 65 + cc] = src[(size_t)r * 512 + cc];
        }
        __syncthreads();
        int w = tid >> 5, lane = tid & 31;
#pragma unroll
        for (int qq = 0; qq < 8; qq++) {
            int q2 = w * 8 + qq;
            uint32_t b0 = __ballot_sync(0xffffffffu, t[lane * 65 + q2] != 0.0f);
            uint32_t b1 = __ballot_sync(0xffffffffu, t[(lane + 32) * 65 + q2] != 0.0f);
            if (lane == 0)
                g_mask[(((size_t)b * 4 + 1) * 512 + qt * 64 + q2) * 8 + gt] =
                    (u64)b0 | ((u64)b1 << 32);
        }
    }
}

// ---------------- fp16x3 proj GEMM (R14-exact: 128x128, 2 blocks/SM) ------
#define PSTAGE_ELEMS 18944   /* A 2*128*40 + B 2*32*136 */
#define PSMEM_BYTES  (3 * PSTAGE_ELEMS * 2)   /* 113664 */

__global__ __launch_bounds__(128, 2) void proj_gemm_kernel() {
    extern __shared__ __half gsm[];
    uint32_t sb = (uint32_t)__cvta_generic_to_shared(gsm);

    int tid  = threadIdx.x;
    int lane = tid & 31;
    int wid  = tid >> 5;
    int wm   = wid & 1;
    int wn   = wid >> 1;

    int m0 = blockIdx.y * 128;
    int n0 = blockIdx.x * 128;
    int skip_lo = ((n0 >> 9) % 3) == 1;

    float acc[4][8][4];
#pragma unroll
    for (int mf = 0; mf < 4; mf++)
#pragma unroll
        for (int nf = 0; nf < 8; nf++)
#pragma unroll
            for (int e = 0; e < 4; e++) acc[mf][nf][e] = 0.f;

    auto issue = [&](int st, int k0) {
        uint32_t stg = sb + (uint32_t)(st * PSTAGE_ELEMS) * 2;
#pragma unroll
        for (int i = 0; i < 8; i++) {
            int idx = tid + i * 128;
            int p   = idx >> 9;
            int rem = idx & 511;
            int row = rem >> 2, chunk = rem & 3;
            cpa16(stg + (uint32_t)(p * 5120 + row * 40 + chunk * 8) * 2,
                  (p ? g_Alo : g_Ahi) + (size_t)(m0 + row) * Dd + k0 + chunk * 8);
        }
#pragma unroll
        for (int i = 0; i < 8; i++) {
            int idx = tid + i * 128;
            int p   = idx >> 9;
            int rem = idx & 511;
            int row = rem >> 4, chunk = rem & 15;
            cpa16(stg + (uint32_t)(10240 + p * 4352 + row * 136 + chunk * 8) * 2,
                  (p ? g_Wlo : g_Whi) + (size_t)(k0 + row) * NCOL + n0 + chunk * 8);
        }
    };

    issue(0, 0); cpa_commit();
    issue(1, 32); cpa_commit();

    for (int i = 0; i < 16; i++) {
        cpa_wait1();
        __syncthreads();
        uint32_t stg = sb + (uint32_t)((i % 3) * PSTAGE_ELEMS) * 2;

#pragma unroll
        for (int ks = 0; ks < 2; ks++) {
            uint32_t a[2][4][4];
#pragma unroll
            for (int p = 0; p < 2; p++)
#pragma unroll
                for (int mf = 0; mf < 4; mf++) {
                    uint32_t off = (uint32_t)(p * 5120 +
                        (wm * 64 + mf * 16 + (lane & 15)) * 40 +
                        ks * 16 + (lane >> 4) * 8) * 2;
                    ldsm4(a[p][mf], stg + off);
                }
#pragma unroll
            for (int pr = 0; pr < 4; pr++) {
                uint32_t bh[4], bl[4];
                uint32_t offh = (uint32_t)(10240 +
                    (ks * 16 + (lane & 15)) * 136 +
                    wn * 64 + pr * 16 + (lane >> 4) * 8) * 2;
                ldsm4t(bh, stg + offh);
                ldsm4t(bl, stg + offh + (uint32_t)4352 * 2);
#pragma unroll
                for (int mf = 0; mf < 4; mf++) {
#pragma unroll
                    for (int hh = 0; hh < 2; hh++) {
                        int nf = 2 * pr + hh;
                        mma_f16(acc[mf][nf], a[0][mf], bh[2 * hh], bh[2 * hh + 1]);
                        mma_f16(acc[mf][nf], a[0][mf], bl[2 * hh], bl[2 * hh + 1]);
                        mma_f16(acc[mf][nf], a[1][mf], bh[2 * hh], bh[2 * hh + 1]);
                    }
                }
            }
        }
        if (i + 2 < 16) issue((i + 2) % 3, (i + 2) * 32);
        cpa_commit();
    }

#pragma unroll
    for (int mf = 0; mf < 4; mf++) {
        int gm = m0 + wm * 64 + mf * 16 + (lane >> 2);
#pragma unroll
        for (int nf = 0; nf < 8; nf++) {
            int gn = n0 + wn * 64 + nf * 8 + (lane & 3) * 2;
            uint32_t h2, l2;
            split_pair(acc[mf][nf][0], acc[mf][nf][1], h2, l2);
            *(uint32_t*)(g_Phi + (size_t)gm * NCOL + gn) = h2;
            if (!skip_lo) *(uint32_t*)(g_Plo + (size_t)gm * NCOL + gn) = l2;
            split_pair(acc[mf][nf][2], acc[mf][nf][3], h2, l2);
            *(uint32_t*)(g_Phi + (size_t)(gm + 8) * NCOL + gn) = h2;
            if (!skip_lo) *(uint32_t*)(g_Plo + (size_t)(gm + 8) * NCOL + gn) = l2;
        }
    }
}

// ---------------- fp16x3 pipelined MMA GEMM (3-stage, output proj) --------
#define GSTAGE_ELEMS 18944          /* 2*128*40 + 2*32*136 */
#define GSMEM_BYTES  (3 * GSTAGE_ELEMS * 2)

__global__ __launch_bounds__(256) void mma_gemm2_kernel(
    const __half* __restrict__ Ahi, const __half* __restrict__ Alo,
    const __half* __restrict__ Bhi, const __half* __restrict__ Blo,
    float* __restrict__ C, int M, int N, int K) {
    extern __shared__ __half gsm[];
    uint32_t sb = (uint32_t)__cvta_generic_to_shared(gsm);

    int tid  = threadIdx.x;
    int lane = tid & 31;
    int wid  = tid >> 5;
    int wm   = wid & 1;
    int wn   = wid >> 1;

    int m0 = blockIdx.y * 128;
    int n0 = blockIdx.x * 128;

    const __half* Ag[2] = { Ahi, Alo };
    const __half* Bg[2] = { Bhi, Blo };

    float acc[4][4][4];
#pragma unroll
    for (int mf = 0; mf < 4; mf++)
#pragma unroll
        for (int nf = 0; nf < 4; nf++)
#pragma unroll
            for (int e = 0; e < 4; e++) acc[mf][nf][e] = 0.f;

    int arow = tid >> 1;
    int achk = tid & 1;
    int brow = tid >> 3;
    int bchk = tid & 7;

    int steps = K >> 5;

    auto issue = [&](int st, int k0) {
        uint32_t stg = sb + (uint32_t)(st * GSTAGE_ELEMS) * 2;
#pragma unroll
        for (int p = 0; p < 2; p++) {
#pragma unroll
            for (int cc = 0; cc < 2; cc++) {
                int chunk = achk + cc * 2;
                cpa16(stg + (uint32_t)(p * 5120 + arow * 40 + chunk * 8) * 2,
                      Ag[p] + (size_t)(m0 + arow) * K + k0 + chunk * 8);
            }
#pragma unroll
            for (int cc = 0; cc < 2; cc++) {
                int chunk = bchk + cc * 8;
                cpa16(stg + (uint32_t)(10240 + p * 4352 + brow * 136 + chunk * 8) * 2,
                      Bg[p] + (size_t)(k0 + brow) * N + n0 + chunk * 8);
            }
        }
    };

    issue(0, 0); cpa_commit();
    issue(1, 32); cpa_commit();

    for (int i = 0; i < steps; i++) {
        cpa_wait1();
        __syncthreads();
        uint32_t stg = sb + (uint32_t)((i % 3) * GSTAGE_ELEMS) * 2;

#pragma unroll
        for (int ks = 0; ks < 2; ks++) {
            uint32_t a[2][4][4];
#pragma unroll
            for (int p = 0; p < 2; p++)
#pragma unroll
                for (int mf = 0; mf < 4; mf++) {
                    uint32_t off = (uint32_t)(p * 5120 +
                        (wm * 64 + mf * 16 + (lane & 15)) * 40 +
                        ks * 16 + (lane >> 4) * 8) * 2;
                    ldsm4(a[p][mf], stg + off);
                }
#pragma unroll
            for (int pr = 0; pr < 2; pr++) {
                uint32_t bh[4], bl[4];
                uint32_t offh = (uint32_t)(10240 +
                    (ks * 16 + (lane & 15)) * 136 +
                    wn * 32 + pr * 16 + (lane >> 4) * 8) * 2;
                ldsm4t(bh, stg + offh);
                ldsm4t(bl, stg + offh + (uint32_t)4352 * 2);
#pragma unroll
                for (int mf = 0; mf < 4; mf++) {
#pragma unroll
                    for (int hh = 0; hh < 2; hh++) {
                        int nf = 2 * pr + hh;
                        mma_f16(acc[mf][nf], a[0][mf], bh[2 * hh], bh[2 * hh + 1]);
                        mma_f16(acc[mf][nf], a[0][mf], bl[2 * hh], bl[2 * hh + 1]);
                        mma_f16(acc[mf][nf], a[1][mf], bh[2 * hh], bh[2 * hh + 1]);
                    }
                }
            }
        }
        if (i + 2 < steps) issue((i + 2) % 3, (i + 2) * 32);
        cpa_commit();
    }

#pragma unroll
    for (int mf = 0; mf < 4; mf++) {
        int gm = m0 + wm * 64 + mf * 16 + (lane >> 2);
#pragma unroll
        for (int nf = 0; nf < 4; nf++) {
            int gn = n0 + wn * 32 + nf * 8 + (lane & 3) * 2;
            *(float2*)(C + (size_t)gm * N + gn) =
                make_float2(acc[mf][nf][0], acc[mf][nf][1]);
            *(float2*)(C + (size_t)(gm + 8) * N + gn) =
                make_float2(acc[mf][nf][2], acc[mf][nf][3]);
        }
    }
}

// ---------------- tensor-core fused attention (fp16, v6: V single-plane) ---
// QK = (Qhi+Qlo)*Khi ; PV = (Phi+Plo)*Vhi. Vlo plane removed entirely.
#define QSTR 72
#define ATTN_SMEM ((2 * 128 + 2 * 64) * QSTR * 2)   /* 55296 B */

__global__ __launch_bounds__(128, 3) void attn_mma_kernel() {
    extern __shared__ __half sm[];
    __half* Qhi = sm;
    __half* Qlo = Qhi + 128 * QSTR;
    __half* Khi = Qlo + 128 * QSTR;
    __half* Vhi = Khi + 64 * QSTR;

    int qt = blockIdx.x;
    int hb = blockIdx.y;
    int b  = hb >> 3;
    int h  = hb & 7;
    int tid  = threadIdx.x;
    int lane = tid & 31;
    int wq   = tid >> 5;

    uint32_t qhi_b = (uint32_t)__cvta_generic_to_shared(Qhi);
    uint32_t qlo_b = (uint32_t)__cvta_generic_to_shared(Qlo);
    uint32_t khi_b = (uint32_t)__cvta_generic_to_shared(Khi);
    uint32_t vhi_b = (uint32_t)__cvta_generic_to_shared(Vhi);

    float o[2][8][4];
    float mrow[2][2], den[2][2];
#pragma unroll
    for (int mf = 0; mf < 2; mf++) {
#pragma unroll
        for (int vf = 0; vf < 8; vf++)
#pragma unroll
            for (int e = 0; e < 4; e++) o[mf][vf][e] = 0.f;
        mrow[mf][0] = mrow[mf][1] = -1e30f;
        den[mf][0] = den[mf][1] = 0.f;
    }

    int ldr = tid >> 3;
    int c8  = tid & 7;
    const __half2 nrm2 = __floats2half2_rn(NORMS, NORMS);

    for (int c = 0; c < 4; c++) {
        __syncthreads();
        {
            size_t qoff = (size_t)(b * 512 + qt * 128) * NCOL + (3 * c) * 512
                          + h * 64 + c8 * 8;
#pragma unroll
            for (int it = 0; it < 8; it++) {
                int row = ldr + it * 16;
                __half2 v[4];
                *(uint4*)v = *(const uint4*)(g_Phi + qoff + (size_t)row * NCOL);
#pragma unroll
                for (int e = 0; e < 4; e++) v[e] = __hmul2(v[e], nrm2);
                *(uint4*)(Qhi + row * QSTR + c8 * 8) = *(uint4*)v;
                *(uint4*)v = *(const uint4*)(g_Plo + qoff + (size_t)row * NCOL);
#pragma unroll
                for (int e = 0; e < 4; e++) v[e] = __hmul2(v[e], nrm2);
                *(uint4*)(Qlo + row * QSTR + c8 * 8) = *(uint4*)v;
            }
        }
        size_t mrow_base = (((size_t)b * 4 + c) * 512 + qt * 128) * 8;

        for (int g0t = 0; g0t < 8; g0t++) {
            __syncthreads();
            {
                size_t gbase = (size_t)(b * 512 + g0t * 64) * NCOL + h * 64 + c8 * 8;
                const __half* KgH = g_Phi + gbase + (3 * c + 1) * 512;
                const __half* VgH = g_Phi + gbase + (3 * c + 2) * 512;
#pragma unroll
                for (int it = 0; it < 4; it++) {
                    int row = ldr + it * 16;
                    *(uint4*)(Khi + row * QSTR + c8 * 8) = *(const uint4*)(KgH + (size_t)row * NCOL);
                    *(uint4*)(Vhi + row * QSTR + c8 * 8) = *(const uint4*)(VgH + (size_t)row * NCOL);
                }
            }
            __syncthreads();

            u64 mw[2][2];
#pragma unroll
            for (int mf = 0; mf < 2; mf++)
#pragma unroll
                for (int hf = 0; hf < 2; hf++) {
                    int ql = wq * 32 + mf * 16 + (lane >> 2) + 8 * hf;
                    mw[mf][hf] = g_mask[mrow_base + (size_t)ql * 8 + g0t];
                }

            float s[2][8][4];
#pragma unroll
            for (int mf = 0; mf < 2; mf++)
#pragma unroll
                for (int nf = 0; nf < 8; nf++)
#pragma unroll
                    for (int e = 0; e < 4; e++) s[mf][nf][e] = 0.f;

#pragma unroll
            for (int ks = 0; ks < 4; ks++) {
                uint32_t ah[2][4], al[2][4];
#pragma unroll
                for (int mf = 0; mf < 2; mf++) {
                    uint32_t off = ((wq * 32 + mf * 16 + (lane & 15)) * QSTR +
                                    ks * 16 + (lane >> 4) * 8) * 2;
                    ldsm4(ah[mf], qhi_b + off);
                    ldsm4(al[mf], qlo_b + off);
                }
#pragma unroll
                for (int pr = 0; pr < 4; pr++) {
                    uint32_t off = ((pr * 16 + (lane & 7) + ((lane >> 4) & 1) * 8) * QSTR +
                                    ks * 16 + ((lane >> 3) & 1) * 8) * 2;
                    uint32_t kh[4];
                    ldsm4(kh, khi_b + off);
#pragma unroll
                    for (int mf = 0; mf < 2; mf++) {
                        mma_f16(s[mf][2 * pr],     ah[mf], kh[0], kh[1]);
                        mma_f16(s[mf][2 * pr],     al[mf], kh[0], kh[1]);
                        mma_f16(s[mf][2 * pr + 1], ah[mf], kh[2], kh[3]);
                        mma_f16(s[mf][2 * pr + 1], al[mf], kh[2], kh[3]);
                    }
                }
            }

#pragma unroll
            for (int mf = 0; mf < 2; mf++)
#pragma unroll
                for (int hf = 0; hf < 2; hf++) {
                    int i0 = 2 * hf;
                    u64 w = mw[mf][hf];
                    int sb2 = 2 * (lane & 3);
                    float rm = -1e30f;
#pragma unroll
                    for (int nf = 0; nf < 8; nf++) {
                        uint32_t bits = (uint32_t)(w >> (nf * 8 + sb2)) & 3u;
                        float v0 = (bits & 1u) ? s[mf][nf][i0] : -1e30f;
                        float v1 = (bits & 2u) ? s[mf][nf][i0 + 1] : -1e30f;
                        s[mf][nf][i0]     = v0;
                        s[mf][nf][i0 + 1] = v1;
                        rm = fmaxf(rm, fmaxf(v0, v1));
                    }
                    rm = fmaxf(rm, __shfl_xor_sync(0xffffffffu, rm, 1));
                    rm = fmaxf(rm, __shfl_xor_sync(0xffffffffu, rm, 2));
                    float mo = mrow[mf][hf];
                    float mn = fmaxf(mo, rm);
                    float rs = 0.f;
#pragma unroll
                    for (int nf = 0; nf < 8; nf++) {
                        float v0 = s[mf][nf][i0];
                        float v1 = s[mf][nf][i0 + 1];
                        float p0 = (v0 > -1e29f) ? __expf(v0 - mn) : 0.f;
                        float p1 = (v1 > -1e29f) ? __expf(v1 - mn) : 0.f;
                        s[mf][nf][i0]     = p0;
                        s[mf][nf][i0 + 1] = p1;
                        rs += p0 + p1;
                    }
                    rs += __shfl_xor_sync(0xffffffffu, rs, 1);
                    rs += __shfl_xor_sync(0xffffffffu, rs, 2);
                    if (mn > mo) {
                        float sc = __expf(mo - mn);
                        den[mf][hf] = den[mf][hf] * sc + rs;
#pragma unroll
                        for (int vf = 0; vf < 8; vf++) {
                            o[mf][vf][i0]     *= sc;
                            o[mf][vf][i0 + 1] *= sc;
                        }
                    } else {
                        den[mf][hf] += rs;
                    }
                    mrow[mf][hf] = mn;
                }

            // ---- O += P V ((Phi+Plo)*Vhi) ----
#pragma unroll
            for (int ks = 0; ks < 4; ks++) {
                uint32_t ph[2][4], pl[2][4];
#pragma unroll
                for (int mf = 0; mf < 2; mf++) {
                    split_pair(s[mf][2 * ks][0],     s[mf][2 * ks][1],     ph[mf][0], pl[mf][0]);
                    split_pair(s[mf][2 * ks][2],     s[mf][2 * ks][3],     ph[mf][1], pl[mf][1]);
                    split_pair(s[mf][2 * ks + 1][0], s[mf][2 * ks + 1][1], ph[mf][2], pl[mf][2]);
                    split_pair(s[mf][2 * ks + 1][2], s[mf][2 * ks + 1][3], ph[mf][3], pl[mf][3]);
                }
#pragma unroll
                for (int pr = 0; pr < 4; pr++) {
                    uint32_t off = ((ks * 16 + (lane & 15)) * QSTR +
                                    pr * 16 + (lane >> 4) * 8) * 2;
                    uint32_t vh[4];
                    ldsm4t(vh, vhi_b + off);
#pragma unroll
                    for (int mf = 0; mf < 2; mf++) {
                        mma_f16(o[mf][2 * pr],     ph[mf], vh[0], vh[1]);
                        mma_f16(o[mf][2 * pr],     pl[mf], vh[0], vh[1]);
                        mma_f16(o[mf][2 * pr + 1], ph[mf], vh[2], vh[3]);
                        mma_f16(o[mf][2 * pr + 1], pl[mf], vh[2], vh[3]);
                    }
                }
            }
        }
        __syncthreads();
    }

#pragma unroll
    for (int mf = 0; mf < 2; mf++)
#pragma unroll
        for (int hf = 0; hf < 2; hf++) {
            int ql = wq * 32 + mf * 16 + (lane >> 2) + 8 * hf;
            float dv = den[mf][hf];
            float inv = (dv > 0.f) ? 1.f / dv : 0.f;
            size_t base = ((size_t)(b * 512 + qt * 128 + ql)) * 512 + h * 64;
#pragma unroll
            for (int vf = 0; vf < 8; vf++) {
                float v0 = o[mf][vf][2 * hf] * inv;
                float v1 = o[mf][vf][2 * hf + 1] * inv;
                uint32_t h2, l2;
                split_pair(v0, v1, h2, l2);
                int col = vf * 8 + 2 * (lane & 3);
                *(uint32_t*)(g_Hhi + base + col) = h2;
                *(uint32_t*)(g_Hlo + base + col) = l2;
            }
        }
}

// ---------------- launch ---------------------------------------------------
extern "C" void kernel_launch(void* const* d_in, const int* in_sizes, int n_in,
                              void* d_out, int out_size) {
    const float* q    = (const float*)d_in[0];
    const float* attM = (const float*)d_in[1];
    const float* grpM = (const float*)d_in[2];
    const float* sdM  = (const float*)d_in[3];
    WPtrs wp;
    for (int i = 0; i < 12; i++) wp.w[i] = (const float*)d_in[4 + i];
    const float* wout = (const float*)d_in[16];
    float* out = (float*)d_out;

    void *pOhi, *pOlo, *pHhi, *pHlo;
    cudaGetSymbolAddress(&pOhi, g_Ohi);
    cudaGetSymbolAddress(&pOlo, g_Olo);
    cudaGetSymbolAddress(&pHhi, g_Hhi);
    cudaGetSymbolAddress(&pHlo, g_Hlo);

    cudaFuncSetAttribute(proj_gemm_kernel,
                         cudaFuncAttributeMaxDynamicSharedMemorySize, PSMEM_BYTES);
    cudaFuncSetAttribute(mma_gemm2_kernel,
                         cudaFuncAttributeMaxDynamicSharedMemorySize, GSMEM_BYTES);
    cudaFuncSetAttribute(attn_mma_kernel,
                         cudaFuncAttributeMaxDynamicSharedMemorySize, ATTN_SMEM);

    // ncu capture slot (index 3) = attention
    // 0: fused prep (weight repack + q split + wout split)
    prep_kernel<<<(int)(PREP_TOTAL / 256), 256>>>(wp, q, wout);
    // 1: all mask packing
    maskall_kernel<<<4096, 256>>>(attM, grpM, sdM);
    // 2: fused projection GEMM -> fp16 hi/lo planes (R14 config)
    proj_gemm_kernel<<<dim3(NCOL / 128, ROWSM / 128), 128, PSMEM_BYTES>>>();
    // 3: tensor-core fused masked 4-branch attention (v6)
    attn_mma_kernel<<<dim3(4, 128), 128, ATTN_SMEM>>>();
    // 4: output GEMM -> fp32 out (3-stage)
    mma_gemm2_kernel<<<dim3(Ee / 128, ROWSM / 128), 256, GSMEM_BYTES>>>(
        (const __half*)pHhi, (const __half*)pHlo,
        (const __half*)pOhi, (const __half*)pOlo,
        out, ROWSM, Ee, Dd);
}

// round 17
// speedup vs baseline: 1.1255x; 1.0872x over previous
#include <cuda_runtime.h>
#include <cuda_fp16.h>
#include <cstdint>

#define Hh   8
#define Bb   16
#define Gg   512
#define NQq  512
#define Dd   512
#define KDd  64
#define Ee   512
#define NCOL 6144           /* 12 * 512 */
#define ROWSM 8192          /* B * NQ   */
#define NORMS 0.125f

typedef unsigned long long u64;

// ---------------- mma.sync / ldmatrix / cp.async helpers -------------------
__device__ __forceinline__ void ldsm4(uint32_t* d, uint32_t addr) {
    asm volatile("ldmatrix.sync.aligned.m8n8.x4.shared.b16 {%0,%1,%2,%3}, [%4];"
                 : "=r"(d[0]), "=r"(d[1]), "=r"(d[2]), "=r"(d[3]) : "r"(addr));
}
__device__ __forceinline__ void ldsm4t(uint32_t* d, uint32_t addr) {
    asm volatile("ldmatrix.sync.aligned.m8n8.x4.trans.shared.b16 {%0,%1,%2,%3}, [%4];"
                 : "=r"(d[0]), "=r"(d[1]), "=r"(d[2]), "=r"(d[3]) : "r"(addr));
}
__device__ __forceinline__ void mma_f16(float* c, const uint32_t* a,
                                        uint32_t b0, uint32_t b1) {
    asm volatile(
        "mma.sync.aligned.m16n8k16.row.col.f32.f16.f16.f32 "
        "{%0,%1,%2,%3}, {%4,%5,%6,%7}, {%8,%9}, {%0,%1,%2,%3};"
        : "+f"(c[0]), "+f"(c[1]), "+f"(c[2]), "+f"(c[3])
        : "r"(a[0]), "r"(a[1]), "r"(a[2]), "r"(a[3]), "r"(b0), "r"(b1));
}
__device__ __forceinline__ void cpa16(uint32_t dst, const void* src) {
    asm volatile("cp.async.cg.shared.global [%0], [%1], 16;"
                 :: "r"(dst), "l"(src));
}
__device__ __forceinline__ void cpa_commit() {
    asm volatile("cp.async.commit_group;" ::: "memory");
}
__device__ __forceinline__ void cpa_wait1() {
    asm volatile("cp.async.wait_group 1;" ::: "memory");
}
// pack two fp32 as half2 (v0 low, v1 high), plus fp16 residual plane
__device__ __forceinline__ void split_pair(float v0, float v1,
                                           uint32_t& hi, uint32_t& lo) {
    __half2 h = __floats2half2_rn(v0, v1);
    float2 hf = __half22float2(h);
    __half2 l = __floats2half2_rn(v0 - hf.x, v1 - hf.y);
    hi = *reinterpret_cast<uint32_t*>(&h);
    lo = *reinterpret_cast<uint32_t*>(&l);
}

// ---------------- device scratch (static: allocation-guard safe) ----------
__device__ __half g_Phi[(size_t)ROWSM * NCOL];  // projections hi
__device__ __half g_Plo[(size_t)ROWSM * NCOL];  // projections lo
__device__ u64 g_mask[(size_t)Bb * 4 * NQq * 8];

__device__ __half g_Ahi[(size_t)ROWSM * Dd];    // q split
__device__ __half g_Alo[(size_t)ROWSM * Dd];
__device__ __half g_Whi[(size_t)Dd * NCOL];     // fused weights split
__device__ __half g_Wlo[(size_t)Dd * NCOL];
__device__ __half g_Ohi[Dd * Ee];               // W_out split
__device__ __half g_Olo[Dd * Ee];
__device__ __half g_Hhi[(size_t)ROWSM * Dd];    // heads split (B,NQ,H,VD)
__device__ __half g_Hlo[(size_t)ROWSM * Dd];

#define NROWS ((size_t)Bb * NQq * Hh)           /* 65536 (b,q,h) rows */
__device__ float  g_po[2 * NROWS * 64];         // partial unnormalized O
__device__ float2 g_pmd[2 * NROWS];             // partial (m, den)

struct WPtrs { const float* w[12]; };

// ---------------- fused prep: weight repack + q split + wout split --------
#define N_REPACK ((size_t)Dd * NCOL)
#define N_QSPLIT ((size_t)ROWSM * Dd)
#define N_OSPLIT ((size_t)Dd * Ee)
#define PREP_TOTAL (N_REPACK + N_QSPLIT + N_OSPLIT)   /* 7602176 */

__global__ void prep_kernel(WPtrs wp, const float* __restrict__ q,
                            const float* __restrict__ wout) {
    size_t idx = (size_t)blockIdx.x * 256 + threadIdx.x;
    if (idx < N_REPACK) {
        int d   = (int)(idx / NCOL);
        int col = (int)(idx - (size_t)d * NCOL);
        int w   = col >> 9;
        int hk  = col & 511;
        int h   = hk >> 6;
        int k   = hk & 63;
        float x = wp.w[w][((size_t)h * Dd + d) * KDd + k];
        __half hi = __float2half_rn(x);
        g_Whi[idx] = hi;
        g_Wlo[idx] = __float2half_rn(x - __half2float(hi));
    } else if (idx < N_REPACK + N_QSPLIT) {
        size_t i = idx - N_REPACK;
        float x = q[i];
        __half h = __float2half_rn(x);
        g_Ahi[i] = h;
        g_Alo[i] = __float2half_rn(x - __half2float(h));
    } else {
        size_t i = idx - N_REPACK - N_QSPLIT;
        float x = wout[i];
        __half h = __float2half_rn(x);
        g_Ohi[i] = h;
        g_Olo[i] = __float2half_rn(x - __half2float(h));
    }
}

// ---------------- fused mask pack: row branches + transposed branch --------
__global__ void maskall_kernel(const float* __restrict__ attm,
                               const float* __restrict__ gmk,
                               const float* __restrict__ sd) {
    __shared__ float t[64 * 65];
    int bx  = blockIdx.x;
    int tid = threadIdx.x;
    if (bx < 3072) {
        int widx = bx * 8 + (tid >> 5);
        int lane = tid & 31;
        int q2 = widx & 511;
        int tt = widx >> 9;
        int br = tt % 3;
        int b  = tt / 3;
        const float* row;
        int c;
        if (br == 0)      { row = sd   + ((size_t)b * 512 + q2) * 512; c = 0; }
        else if (br == 1) { row = attm + ((size_t)b * 512 + q2) * 512; c = 2; }
        else              { row = gmk  + ((size_t)b * 512 + q2) * 512; c = 3; }
#pragma unroll
        for (int tile = 0; tile < 8; tile++) {
            uint32_t b0 = __ballot_sync(0xffffffffu, row[tile * 64 + lane] != 0.0f);
            uint32_t b1 = __ballot_sync(0xffffffffu, row[tile * 64 + 32 + lane] != 0.0f);
            if (lane == 0)
                g_mask[(((size_t)b * 4 + c) * 512 + q2) * 8 + tile] =
                    (u64)b0 | ((u64)b1 << 32);
        }
    } else {
        int l  = bx - 3072;
        int gt = l & 7;
        int qt = (l >> 3) & 7;
        int b  = l >> 6;
        const float* src = attm + ((size_t)b * 512 + gt * 64) * 512 + qt * 64;
#pragma unroll
        for (int it = 0; it < 16; it++) {
            int idx = tid + it * 256;
            int r = idx >> 6, cc = idx & 63;
            t[r * 65 + cc] = src[(size_t)r * 512 + cc];
        }
        __syncthreads();
        int w = tid >> 5, lane = tid & 31;
#pragma unroll
        for (int qq = 0; qq < 8; qq++) {
            int q2 = w * 8 + qq;
            uint32_t b0 = __ballot_sync(0xffffffffu, t[lane * 65 + q2] != 0.0f);
            uint32_t b1 = __ballot_sync(0xffffffffu, t[(lane + 32) * 65 + q2] != 0.0f);
            if (lane == 0)
                g_mask[(((size_t)b * 4 + 1) * 512 + qt * 64 + q2) * 8 + gt] =
                    (u64)b0 | ((u64)b1 << 32);
        }
    }
}

// ---------------- fp16x3 proj GEMM (R14-exact: 128x128, 2 blocks/SM) ------
#define PSTAGE_ELEMS 18944   /* A 2*128*40 + B 2*32*136 */
#define PSMEM_BYTES  (3 * PSTAGE_ELEMS * 2)   /* 113664 */

__global__ __launch_bounds__(128, 2) void proj_gemm_kernel() {
    extern __shared__ __half gsm[];
    uint32_t sb = (uint32_t)__cvta_generic_to_shared(gsm);

    int tid  = threadIdx.x;
    int lane = tid & 31;
    int wid  = tid >> 5;
    int wm   = wid & 1;
    int wn   = wid >> 1;

    int m0 = blockIdx.y * 128;
    int n0 = blockIdx.x * 128;
    int skip_lo = ((n0 >> 9) % 3) == 1;

    float acc[4][8][4];
#pragma unroll
    for (int mf = 0; mf < 4; mf++)
#pragma unroll
        for (int nf = 0; nf < 8; nf++)
#pragma unroll
            for (int e = 0; e < 4; e++) acc[mf][nf][e] = 0.f;

    auto issue = [&](int st, int k0) {
        uint32_t stg = sb + (uint32_t)(st * PSTAGE_ELEMS) * 2;
#pragma unroll
        for (int i = 0; i < 8; i++) {
            int idx = tid + i * 128;
            int p   = idx >> 9;
            int rem = idx & 511;
            int row = rem >> 2, chunk = rem & 3;
            cpa16(stg + (uint32_t)(p * 5120 + row * 40 + chunk * 8) * 2,
                  (p ? g_Alo : g_Ahi) + (size_t)(m0 + row) * Dd + k0 + chunk * 8);
        }
#pragma unroll
        for (int i = 0; i < 8; i++) {
            int idx = tid + i * 128;
            int p   = idx >> 9;
            int rem = idx & 511;
            int row = rem >> 4, chunk = rem & 15;
            cpa16(stg + (uint32_t)(10240 + p * 4352 + row * 136 + chunk * 8) * 2,
                  (p ? g_Wlo : g_Whi) + (size_t)(k0 + row) * NCOL + n0 + chunk * 8);
        }
    };

    issue(0, 0); cpa_commit();
    issue(1, 32); cpa_commit();

    for (int i = 0; i < 16; i++) {
        cpa_wait1();
        __syncthreads();
        uint32_t stg = sb + (uint32_t)((i % 3) * PSTAGE_ELEMS) * 2;

#pragma unroll
        for (int ks = 0; ks < 2; ks++) {
            uint32_t a[2][4][4];
#pragma unroll
            for (int p = 0; p < 2; p++)
#pragma unroll
                for (int mf = 0; mf < 4; mf++) {
                    uint32_t off = (uint32_t)(p * 5120 +
                        (wm * 64 + mf * 16 + (lane & 15)) * 40 +
                        ks * 16 + (lane >> 4) * 8) * 2;
                    ldsm4(a[p][mf], stg + off);
                }
#pragma unroll
            for (int pr = 0; pr < 4; pr++) {
                uint32_t bh[4], bl[4];
                uint32_t offh = (uint32_t)(10240 +
                    (ks * 16 + (lane & 15)) * 136 +
                    wn * 64 + pr * 16 + (lane >> 4) * 8) * 2;
                ldsm4t(bh, stg + offh);
                ldsm4t(bl, stg + offh + (uint32_t)4352 * 2);
#pragma unroll
                for (int mf = 0; mf < 4; mf++) {
#pragma unroll
                    for (int hh = 0; hh < 2; hh++) {
                        int nf = 2 * pr + hh;
                        mma_f16(acc[mf][nf], a[0][mf], bh[2 * hh], bh[2 * hh + 1]);
                        mma_f16(acc[mf][nf], a[0][mf], bl[2 * hh], bl[2 * hh + 1]);
                        mma_f16(acc[mf][nf], a[1][mf], bh[2 * hh], bh[2 * hh + 1]);
                    }
                }
            }
        }
        if (i + 2 < 16) issue((i + 2) % 3, (i + 2) * 32);
        cpa_commit();
    }

#pragma unroll
    for (int mf = 0; mf < 4; mf++) {
        int gm = m0 + wm * 64 + mf * 16 + (lane >> 2);
#pragma unroll
        for (int nf = 0; nf < 8; nf++) {
            int gn = n0 + wn * 64 + nf * 8 + (lane & 3) * 2;
            uint32_t h2, l2;
            split_pair(acc[mf][nf][0], acc[mf][nf][1], h2, l2);
            *(uint32_t*)(g_Phi + (size_t)gm * NCOL + gn) = h2;
            if (!skip_lo) *(uint32_t*)(g_Plo + (size_t)gm * NCOL + gn) = l2;
            split_pair(acc[mf][nf][2], acc[mf][nf][3], h2, l2);
            *(uint32_t*)(g_Phi + (size_t)(gm + 8) * NCOL + gn) = h2;
            if (!skip_lo) *(uint32_t*)(g_Plo + (size_t)(gm + 8) * NCOL + gn) = l2;
        }
    }
}

// ---------------- fp16x3 pipelined MMA GEMM (3-stage, output proj) --------
#define GSTAGE_ELEMS 18944          /* 2*128*40 + 2*32*136 */
#define GSMEM_BYTES  (3 * GSTAGE_ELEMS * 2)

__global__ __launch_bounds__(256) void mma_gemm2_kernel(
    const __half* __restrict__ Ahi, const __half* __restrict__ Alo,
    const __half* __restrict__ Bhi, const __half* __restrict__ Blo,
    float* __restrict__ C, int M, int N, int K) {
    extern __shared__ __half gsm[];
    uint32_t sb = (uint32_t)__cvta_generic_to_shared(gsm);

    int tid  = threadIdx.x;
    int lane = tid & 31;
    int wid  = tid >> 5;
    int wm   = wid & 1;
    int wn   = wid >> 1;

    int m0 = blockIdx.y * 128;
    int n0 = blockIdx.x * 128;

    const __half* Ag[2] = { Ahi, Alo };
    const __half* Bg[2] = { Bhi, Blo };

    float acc[4][4][4];
#pragma unroll
    for (int mf = 0; mf < 4; mf++)
#pragma unroll
        for (int nf = 0; nf < 4; nf++)
#pragma unroll
            for (int e = 0; e < 4; e++) acc[mf][nf][e] = 0.f;

    int arow = tid >> 1;
    int achk = tid & 1;
    int brow = tid >> 3;
    int bchk = tid & 7;

    int steps = K >> 5;

    auto issue = [&](int st, int k0) {
        uint32_t stg = sb + (uint32_t)(st * GSTAGE_ELEMS) * 2;
#pragma unroll
        for (int p = 0; p < 2; p++) {
#pragma unroll
            for (int cc = 0; cc < 2; cc++) {
                int chunk = achk + cc * 2;
                cpa16(stg + (uint32_t)(p * 5120 + arow * 40 + chunk * 8) * 2,
                      Ag[p] + (size_t)(m0 + arow) * K + k0 + chunk * 8);
            }
#pragma unroll
            for (int cc = 0; cc < 2; cc++) {
                int chunk = bchk + cc * 8;
                cpa16(stg + (uint32_t)(10240 + p * 4352 + brow * 136 + chunk * 8) * 2,
                      Bg[p] + (size_t)(k0 + brow) * N + n0 + chunk * 8);
            }
        }
    };

    issue(0, 0); cpa_commit();
    issue(1, 32); cpa_commit();

    for (int i = 0; i < steps; i++) {
        cpa_wait1();
        __syncthreads();
        uint32_t stg = sb + (uint32_t)((i % 3) * GSTAGE_ELEMS) * 2;

#pragma unroll
        for (int ks = 0; ks < 2; ks++) {
            uint32_t a[2][4][4];
#pragma unroll
            for (int p = 0; p < 2; p++)
#pragma unroll
                for (int mf = 0; mf < 4; mf++) {
                    uint32_t off = (uint32_t)(p * 5120 +
                        (wm * 64 + mf * 16 + (lane & 15)) * 40 +
                        ks * 16 + (lane >> 4) * 8) * 2;
                    ldsm4(a[p][mf], stg + off);
                }
#pragma unroll
            for (int pr = 0; pr < 2; pr++) {
                uint32_t bh[4], bl[4];
                uint32_t offh = (uint32_t)(10240 +
                    (ks * 16 + (lane & 15)) * 136 +
                    wn * 32 + pr * 16 + (lane >> 4) * 8) * 2;
                ldsm4t(bh, stg + offh);
                ldsm4t(bl, stg + offh + (uint32_t)4352 * 2);
#pragma unroll
                for (int mf = 0; mf < 4; mf++) {
#pragma unroll
                    for (int hh = 0; hh < 2; hh++) {
                        int nf = 2 * pr + hh;
                        mma_f16(acc[mf][nf], a[0][mf], bh[2 * hh], bh[2 * hh + 1]);
                        mma_f16(acc[mf][nf], a[0][mf], bl[2 * hh], bl[2 * hh + 1]);
                        mma_f16(acc[mf][nf], a[1][mf], bh[2 * hh], bh[2 * hh + 1]);
                    }
                }
            }
        }
        if (i + 2 < steps) issue((i + 2) % 3, (i + 2) * 32);
        cpa_commit();
    }

#pragma unroll
    for (int mf = 0; mf < 4; mf++) {
        int gm = m0 + wm * 64 + mf * 16 + (lane >> 2);
#pragma unroll
        for (int nf = 0; nf < 4; nf++) {
            int gn = n0 + wn * 32 + nf * 8 + (lane & 3) * 2;
            *(float2*)(C + (size_t)gm * N + gn) =
                make_float2(acc[mf][nf][0], acc[mf][nf][1]);
            *(float2*)(C + (size_t)(gm + 8) * N + gn) =
                make_float2(acc[mf][nf][2], acc[mf][nf][3]);
        }
    }
}

// ---------------- tensor-core fused attention (fp16, v7: 2-branch split) ---
// grid (4,128,2): part p handles branches {2p, 2p+1}; partial (o,m,den) -> gmem.
#define QSTR 72
#define ATTN_SMEM ((2 * 128 + 2 * 64) * QSTR * 2)   /* 55296 B */

__global__ __launch_bounds__(128, 3) void attn_mma_kernel() {
    extern __shared__ __half sm[];
    __half* Qhi = sm;
    __half* Qlo = Qhi + 128 * QSTR;
    __half* Khi = Qlo + 128 * QSTR;
    __half* Vhi = Khi + 64 * QSTR;

    int qt = blockIdx.x;
    int hb = blockIdx.y;
    int part = blockIdx.z;             // 0 or 1
    int b  = hb >> 3;
    int h  = hb & 7;
    int tid  = threadIdx.x;
    int lane = tid & 31;
    int wq   = tid >> 5;

    uint32_t qhi_b = (uint32_t)__cvta_generic_to_shared(Qhi);
    uint32_t qlo_b = (uint32_t)__cvta_generic_to_shared(Qlo);
    uint32_t khi_b = (uint32_t)__cvta_generic_to_shared(Khi);
    uint32_t vhi_b = (uint32_t)__cvta_generic_to_shared(Vhi);

    float o[2][8][4];
    float mrow[2][2], den[2][2];
#pragma unroll
    for (int mf = 0; mf < 2; mf++) {
#pragma unroll
        for (int vf = 0; vf < 8; vf++)
#pragma unroll
            for (int e = 0; e < 4; e++) o[mf][vf][e] = 0.f;
        mrow[mf][0] = mrow[mf][1] = -1e30f;
        den[mf][0] = den[mf][1] = 0.f;
    }

    int ldr = tid >> 3;
    int c8  = tid & 7;
    const __half2 nrm2 = __floats2half2_rn(NORMS, NORMS);

    for (int ci = 0; ci < 2; ci++) {
        int c = part * 2 + ci;
        __syncthreads();
        {
            size_t qoff = (size_t)(b * 512 + qt * 128) * NCOL + (3 * c) * 512
                          + h * 64 + c8 * 8;
#pragma unroll
            for (int it = 0; it < 8; it++) {
                int row = ldr + it * 16;
                __half2 v[4];
                *(uint4*)v = *(const uint4*)(g_Phi + qoff + (size_t)row * NCOL);
#pragma unroll
                for (int e = 0; e < 4; e++) v[e] = __hmul2(v[e], nrm2);
                *(uint4*)(Qhi + row * QSTR + c8 * 8) = *(uint4*)v;
                *(uint4*)v = *(const uint4*)(g_Plo + qoff + (size_t)row * NCOL);
#pragma unroll
                for (int e = 0; e < 4; e++) v[e] = __hmul2(v[e], nrm2);
                *(uint4*)(Qlo + row * QSTR + c8 * 8) = *(uint4*)v;
            }
        }
        size_t mrow_base = (((size_t)b * 4 + c) * 512 + qt * 128) * 8;

        for (int g0t = 0; g0t < 8; g0t++) {
            __syncthreads();
            {
                size_t gbase = (size_t)(b * 512 + g0t * 64) * NCOL + h * 64 + c8 * 8;
                const __half* KgH = g_Phi + gbase + (3 * c + 1) * 512;
                const __half* VgH = g_Phi + gbase + (3 * c + 2) * 512;
#pragma unroll
                for (int it = 0; it < 4; it++) {
                    int row = ldr + it * 16;
                    *(uint4*)(Khi + row * QSTR + c8 * 8) = *(const uint4*)(KgH + (size_t)row * NCOL);
                    *(uint4*)(Vhi + row * QSTR + c8 * 8) = *(const uint4*)(VgH + (size_t)row * NCOL);
                }
            }
            __syncthreads();

            u64 mw[2][2];
#pragma unroll
            for (int mf = 0; mf < 2; mf++)
#pragma unroll
                for (int hf = 0; hf < 2; hf++) {
                    int ql = wq * 32 + mf * 16 + (lane >> 2) + 8 * hf;
                    mw[mf][hf] = g_mask[mrow_base + (size_t)ql * 8 + g0t];
                }

            float s[2][8][4];
#pragma unroll
            for (int mf = 0; mf < 2; mf++)
#pragma unroll
                for (int nf = 0; nf < 8; nf++)
#pragma unroll
                    for (int e = 0; e < 4; e++) s[mf][nf][e] = 0.f;

#pragma unroll
            for (int ks = 0; ks < 4; ks++) {
                uint32_t ah[2][4], al[2][4];
#pragma unroll
                for (int mf = 0; mf < 2; mf++) {
                    uint32_t off = ((wq * 32 + mf * 16 + (lane & 15)) * QSTR +
                                    ks * 16 + (lane >> 4) * 8) * 2;
                    ldsm4(ah[mf], qhi_b + off);
                    ldsm4(al[mf], qlo_b + off);
                }
#pragma unroll
                for (int pr = 0; pr < 4; pr++) {
                    uint32_t off = ((pr * 16 + (lane & 7) + ((lane >> 4) & 1) * 8) * QSTR +
                                    ks * 16 + ((lane >> 3) & 1) * 8) * 2;
                    uint32_t kh[4];
                    ldsm4(kh, khi_b + off);
#pragma unroll
                    for (int mf = 0; mf < 2; mf++) {
                        mma_f16(s[mf][2 * pr],     ah[mf], kh[0], kh[1]);
                        mma_f16(s[mf][2 * pr],     al[mf], kh[0], kh[1]);
                        mma_f16(s[mf][2 * pr + 1], ah[mf], kh[2], kh[3]);
                        mma_f16(s[mf][2 * pr + 1], al[mf], kh[2], kh[3]);
                    }
                }
            }

#pragma unroll
            for (int mf = 0; mf < 2; mf++)
#pragma unroll
                for (int hf = 0; hf < 2; hf++) {
                    int i0 = 2 * hf;
                    u64 w = mw[mf][hf];
                    int sb2 = 2 * (lane & 3);
                    float rm = -1e30f;
#pragma unroll
                    for (int nf = 0; nf < 8; nf++) {
                        uint32_t bits = (uint32_t)(w >> (nf * 8 + sb2)) & 3u;
                        float v0 = (bits & 1u) ? s[mf][nf][i0] : -1e30f;
                        float v1 = (bits & 2u) ? s[mf][nf][i0 + 1] : -1e30f;
                        s[mf][nf][i0]     = v0;
                        s[mf][nf][i0 + 1] = v1;
                        rm = fmaxf(rm, fmaxf(v0, v1));
                    }
                    rm = fmaxf(rm, __shfl_xor_sync(0xffffffffu, rm, 1));
                    rm = fmaxf(rm, __shfl_xor_sync(0xffffffffu, rm, 2));
                    float mo = mrow[mf][hf];
                    float mn = fmaxf(mo, rm);
                    float rs = 0.f;
#pragma unroll
                    for (int nf = 0; nf < 8; nf++) {
                        float v0 = s[mf][nf][i0];
                        float v1 = s[mf][nf][i0 + 1];
                        float p0 = (v0 > -1e29f) ? __expf(v0 - mn) : 0.f;
                        float p1 = (v1 > -1e29f) ? __expf(v1 - mn) : 0.f;
                        s[mf][nf][i0]     = p0;
                        s[mf][nf][i0 + 1] = p1;
                        rs += p0 + p1;
                    }
                    rs += __shfl_xor_sync(0xffffffffu, rs, 1);
                    rs += __shfl_xor_sync(0xffffffffu, rs, 2);
                    if (mn > mo) {
                        float sc = __expf(mo - mn);
                        den[mf][hf] = den[mf][hf] * sc + rs;
#pragma unroll
                        for (int vf = 0; vf < 8; vf++) {
                            o[mf][vf][i0]     *= sc;
                            o[mf][vf][i0 + 1] *= sc;
                        }
                    } else {
                        den[mf][hf] += rs;
                    }
                    mrow[mf][hf] = mn;
                }

            // ---- O += P V ((Phi+Plo)*Vhi) ----
#pragma unroll
            for (int ks = 0; ks < 4; ks++) {
                uint32_t ph[2][4], pl[2][4];
#pragma unroll
                for (int mf = 0; mf < 2; mf++) {
                    split_pair(s[mf][2 * ks][0],     s[mf][2 * ks][1],     ph[mf][0], pl[mf][0]);
                    split_pair(s[mf][2 * ks][2],     s[mf][2 * ks][3],     ph[mf][1], pl[mf][1]);
                    split_pair(s[mf][2 * ks + 1][0], s[mf][2 * ks + 1][1], ph[mf][2], pl[mf][2]);
                    split_pair(s[mf][2 * ks + 1][2], s[mf][2 * ks + 1][3], ph[mf][3], pl[mf][3]);
                }
#pragma unroll
                for (int pr = 0; pr < 4; pr++) {
                    uint32_t off = ((ks * 16 + (lane & 15)) * QSTR +
                                    pr * 16 + (lane >> 4) * 8) * 2;
                    uint32_t vh[4];
                    ldsm4t(vh, vhi_b + off);
#pragma unroll
                    for (int mf = 0; mf < 2; mf++) {
                        mma_f16(o[mf][2 * pr],     ph[mf], vh[0], vh[1]);
                        mma_f16(o[mf][2 * pr],     pl[mf], vh[0], vh[1]);
                        mma_f16(o[mf][2 * pr + 1], ph[mf], vh[2], vh[3]);
                        mma_f16(o[mf][2 * pr + 1], pl[mf], vh[2], vh[3]);
                    }
                }
            }
        }
        __syncthreads();
    }

    // epilogue: write unnormalized partials (o, m, den)
#pragma unroll
    for (int mf = 0; mf < 2; mf++)
#pragma unroll
        for (int hf = 0; hf < 2; hf++) {
            int ql = wq * 32 + mf * 16 + (lane >> 2) + 8 * hf;
            size_t r = (((size_t)part * Bb + b) * 512 + qt * 128 + ql) * 8 + h;
            float* base = g_po + r * 64;
#pragma unroll
            for (int vf = 0; vf < 8; vf++)
                *(float2*)(base + vf * 8 + 2 * (lane & 3)) =
                    make_float2(o[mf][vf][2 * hf], o[mf][vf][2 * hf + 1]);
            if ((lane & 3) == 0)
                g_pmd[r] = make_float2(mrow[mf][hf], den[mf][hf]);
        }
}

// ---------------- combine partials -> fp16 hi/lo heads ---------------------
__global__ void combine_kernel() {
    int tid  = threadIdx.x;
    size_t r = (size_t)blockIdx.x * 8 + (tid >> 5);   // 0..65535
    int lane = tid & 31;
    float2 md0 = g_pmd[r];
    float2 md1 = g_pmd[NROWS + r];
    float mstar = fmaxf(md0.x, md1.x);
    float s0 = __expf(md0.x - mstar);
    float s1 = __expf(md1.x - mstar);
    float dn = md0.y * s0 + md1.y * s1;
    float inv = (dn > 0.f) ? 1.f / dn : 0.f;
    float2 a = *(const float2*)(g_po + r * 64 + lane * 2);
    float2 bb2 = *(const float2*)(g_po + (NROWS + r) * 64 + lane * 2);
    float v0 = (a.x * s0 + bb2.x * s1) * inv;
    float v1 = (a.y * s0 + bb2.y * s1) * inv;
    uint32_t h2, l2;
    split_pair(v0, v1, h2, l2);
    size_t bq = r >> 3;
    int h = (int)(r & 7);
    size_t base = bq * 512 + h * 64 + lane * 2;
    *(uint32_t*)(g_Hhi + base) = h2;
    *(uint32_t*)(g_Hlo + base) = l2;
}

// ---------------- launch ---------------------------------------------------
extern "C" void kernel_launch(void* const* d_in, const int* in_sizes, int n_in,
                              void* d_out, int out_size) {
    const float* q    = (const float*)d_in[0];
    const float* attM = (const float*)d_in[1];
    const float* grpM = (const float*)d_in[2];
    const float* sdM  = (const float*)d_in[3];
    WPtrs wp;
    for (int i = 0; i < 12; i++) wp.w[i] = (const float*)d_in[4 + i];
    const float* wout = (const float*)d_in[16];
    float* out = (float*)d_out;

    void *pOhi, *pOlo, *pHhi, *pHlo;
    cudaGetSymbolAddress(&pOhi, g_Ohi);
    cudaGetSymbolAddress(&pOlo, g_Olo);
    cudaGetSymbolAddress(&pHhi, g_Hhi);
    cudaGetSymbolAddress(&pHlo, g_Hlo);

    cudaFuncSetAttribute(proj_gemm_kernel,
                         cudaFuncAttributeMaxDynamicSharedMemorySize, PSMEM_BYTES);
    cudaFuncSetAttribute(mma_gemm2_kernel,
                         cudaFuncAttributeMaxDynamicSharedMemorySize, GSMEM_BYTES);
    cudaFuncSetAttribute(attn_mma_kernel,
                         cudaFuncAttributeMaxDynamicSharedMemorySize, ATTN_SMEM);

    // ncu capture slot (index 3) = attention
    // 0: fused prep (weight repack + q split + wout split)
    prep_kernel<<<(int)(PREP_TOTAL / 256), 256>>>(wp, q, wout);
    // 1: all mask packing
    maskall_kernel<<<4096, 256>>>(attM, grpM, sdM);
    // 2: fused projection GEMM -> fp16 hi/lo planes
    proj_gemm_kernel<<<dim3(NCOL / 128, ROWSM / 128), 128, PSMEM_BYTES>>>();
    // 3: attention, 2-branch split partials (1024 blocks)
    attn_mma_kernel<<<dim3(4, 128, 2), 128, ATTN_SMEM>>>();
    // 4: combine partials -> heads
    combine_kernel<<<(int)(NROWS / 8), 256>>>();
    // 5: output GEMM -> fp32 out
    mma_gemm2_kernel<<<dim3(Ee / 128, ROWSM / 128), 256, GSMEM_BYTES>>>(
        (const __half*)pHhi, (const __half*)pHlo,
        (const __half*)pOhi, (const __half*)pOlo,
        out, ROWSM, Ee, Dd);
}